// round 6
// baseline (speedup 1.0000x reference)
#include <cuda_runtime.h>
#include <cuda_fp16.h>
#include <cstdint>

#define E_ 8
#define T_ 4096
#define D_ 1024
#define F_ 4096
#define CAP 2048
#define NSLOT (E_*CAP)
#define MT_ 16
#define BK 64

// ---------------- static scratch ----------------
__device__ __align__(16) __half g_w1h[(size_t)E_*D_*2*F_];   // [e][k][2j+u] gate/up interleaved
__device__ __align__(16) __half g_w2h[(size_t)E_*F_*D_];     // [e][k][n]
__device__ __align__(16) __half g_xg [(size_t)NSLOT*D_];     // gathered x (fp16)
__device__ __align__(16) __half g_act[(size_t)NSLOT*F_];     // intermediate act
__device__ int   g_cnt[E_];
__device__ int   g_tok[NSLOT];
__device__ float g_coef[NSLOT];
__device__ int   g_slot[2*T_];

// ---------------- helpers ----------------
__device__ __forceinline__ unsigned smem_u32(const void* p){
    return (unsigned)__cvta_generic_to_shared(p);
}
__device__ __forceinline__ void cp16s(unsigned s, const void* g){
    asm volatile("cp.async.cg.shared.global [%0], [%1], 16;\n" :: "r"(s), "l"(g));
}
__device__ __forceinline__ void cp_commit(){ asm volatile("cp.async.commit_group;\n"); }

__device__ __forceinline__ void ldsm4(unsigned&r0,unsigned&r1,unsigned&r2,unsigned&r3,unsigned a){
    asm volatile("ldmatrix.sync.aligned.m8n8.x4.shared.b16 {%0,%1,%2,%3}, [%4];\n"
        : "=r"(r0),"=r"(r1),"=r"(r2),"=r"(r3) : "r"(a));
}
__device__ __forceinline__ void ldsm4t(unsigned&r0,unsigned&r1,unsigned&r2,unsigned&r3,unsigned a){
    asm volatile("ldmatrix.sync.aligned.m8n8.x4.trans.shared.b16 {%0,%1,%2,%3}, [%4];\n"
        : "=r"(r0),"=r"(r1),"=r"(r2),"=r"(r3) : "r"(a));
}
__device__ __forceinline__ void mma16816(float* c, unsigned a0,unsigned a1,unsigned a2,unsigned a3,
                                         unsigned b0,unsigned b1){
    asm volatile("mma.sync.aligned.m16n8k16.row.col.f32.f16.f16.f32 "
        "{%0,%1,%2,%3},{%4,%5,%6,%7},{%8,%9},{%0,%1,%2,%3};\n"
        : "+f"(c[0]),"+f"(c[1]),"+f"(c[2]),"+f"(c[3])
        : "r"(a0),"r"(a1),"r"(a2),"r"(a3),"r"(b0),"r"(b1));
}

__device__ __forceinline__ unsigned swA(int r, int c){   // A: 128 x 64 halves, c in [0,8)
    return (unsigned)(r*128 + ((c ^ (r & 7)) << 4));
}
template<int BNH>
__device__ __forceinline__ unsigned swB(int r, int c){   // B: 64 x BNH halves, c in [0,BNH/8)
    return (unsigned)(r*(BNH*2) + ((c >> 3) << 7) + (((c & 7) ^ (r & 7)) << 4));
}

// ---------------- zero output ----------------
__global__ void k_zero(float* __restrict__ out){
    int i = blockIdx.x*blockDim.x + threadIdx.x;
    float4 z = {0.f,0.f,0.f,0.f};
    ((float4*)out)[i] = z;
}

// ---------------- routing (softmax top-2, renormalized) ----------------
__global__ void k_route(const float* __restrict__ gate){
    int t = blockIdx.x*blockDim.x + threadIdx.x;
    if (t >= T_) return;
    float g[E_];
    #pragma unroll
    for (int i=0;i<E_;i++) g[i] = gate[t*E_+i];
    int i1 = 0; float m1 = g[0];
    #pragma unroll
    for (int i=1;i<E_;i++) if (g[i] > m1){ m1 = g[i]; i1 = i; }
    int i2 = -1; float m2 = -1e30f;
    #pragma unroll
    for (int i=0;i<E_;i++){ if (i==i1) continue; if (g[i] > m2){ m2 = g[i]; i2 = i; } }
    float e2 = expf(m2 - m1);
    float w1 = 1.0f/(1.0f + e2);
    float w2 = e2*w1;
    int p1 = atomicAdd(&g_cnt[i1], 1);
    int s1 = i1*CAP + p1;
    g_tok[s1] = t; g_coef[s1] = w1; g_slot[2*t] = s1;
    int p2 = atomicAdd(&g_cnt[i2], 1);
    int s2 = i2*CAP + p2;
    g_tok[s2] = t; g_coef[s2] = w2; g_slot[2*t+1] = s2;
}

// ---------------- gather x rows + zero-pad, fused ----------------
__global__ void k_gatherpad(const float* __restrict__ x){
    int b = blockIdx.x;
    int tid = threadIdx.x;
    if (b < T_){
        int t = b;
        int s1 = g_slot[2*t], s2 = g_slot[2*t+1];
        const float4* src = (const float4*)(x + (size_t)t*D_);
        __half2* d1 = (__half2*)(g_xg + (size_t)s1*D_);
        __half2* d2 = (__half2*)(g_xg + (size_t)s2*D_);
        float4 a = src[tid*2], c = src[tid*2+1];
        __half2 h0 = __floats2half2_rn(a.x, a.y);
        __half2 h1 = __floats2half2_rn(a.z, a.w);
        __half2 h2 = __floats2half2_rn(c.x, c.y);
        __half2 h3 = __floats2half2_rn(c.z, c.w);
        d1[tid*4+0]=h0; d1[tid*4+1]=h1; d1[tid*4+2]=h2; d1[tid*4+3]=h3;
        d2[tid*4+0]=h0; d2[tid*4+1]=h1; d2[tid*4+2]=h2; d2[tid*4+3]=h3;
    } else {
        int p = b - T_;            // 8 blocks per expert
        int e = p >> 3, sub = p & 7;
        int cnt = g_cnt[e];
        int end = (cnt + 127) & ~127;
        int n2 = (end - cnt)*D_/2;
        __half2* pp = (__half2*)(g_xg + ((size_t)e*CAP + cnt)*D_);
        __half2 z = __float2half2_rn(0.f);
        for (int i = sub*128 + tid; i < n2; i += 1024) pp[i] = z;
    }
}

// ---------------- dequant w1 (interleave gate/up) + zero expert counts ----------------
__global__ void k_dq1(const int* __restrict__ q, const float* __restrict__ s){
    if (blockIdx.x == 0 && threadIdx.x < E_) g_cnt[threadIdx.x] = 0;
    size_t gid = (size_t)blockIdx.x*blockDim.x + threadIdx.x;  // 8388608
    int c8 = (int)(gid & 1023);
    size_t kl = gid >> 10;                 // e*1024 + k
    int k = (int)(kl & 1023); int e = (int)(kl >> 10);
    int j0 = c8*4;
    const int4 gq = *(const int4*)(q + kl*8192 + j0);
    const int4 uq = *(const int4*)(q + kl*8192 + 4096 + j0);
    size_t sb = ((size_t)e*8 + (k>>7))*8192;
    const float4 sg = *(const float4*)(s + sb + j0);
    const float4 su = *(const float4*)(s + sb + 4096 + j0);
    __half2 o[4];
    o[0] = __floats2half2_rn((gq.x-8)*sg.x, (uq.x-8)*su.x);
    o[1] = __floats2half2_rn((gq.y-8)*sg.y, (uq.y-8)*su.y);
    o[2] = __floats2half2_rn((gq.z-8)*sg.z, (uq.z-8)*su.z);
    o[3] = __floats2half2_rn((gq.w-8)*sg.w, (uq.w-8)*su.w);
    *(uint4*)(g_w1h + kl*8192 + (size_t)c8*8) = *(uint4*)o;
}

// ---------------- dequant w2 ----------------
__global__ void k_dq2(const int* __restrict__ q, const float* __restrict__ s){
    size_t gid = (size_t)blockIdx.x*blockDim.x + threadIdx.x;  // 4194304
    int n8 = (int)(gid & 127);
    size_t kl = gid >> 7;                  // e*4096 + k
    int k = (int)(kl & 4095); int e = (int)(kl >> 12);
    int n0 = n8*8;
    const int4 qa = *(const int4*)(q + kl*1024 + n0);
    const int4 qb = *(const int4*)(q + kl*1024 + n0 + 4);
    size_t sbase = ((size_t)e*32 + (k>>7))*1024;
    const float4 sa = *(const float4*)(s + sbase + n0);
    const float4 sb = *(const float4*)(s + sbase + n0 + 4);
    __half2 o[4];
    o[0] = __floats2half2_rn((qa.x-8)*sa.x, (qa.y-8)*sa.y);
    o[1] = __floats2half2_rn((qa.z-8)*sa.z, (qa.w-8)*sa.w);
    o[2] = __floats2half2_rn((qb.x-8)*sb.x, (qb.y-8)*sb.y);
    o[3] = __floats2half2_rn((qb.z-8)*sb.z, (qb.w-8)*sb.w);
    *(uint4*)(g_w2h + kl*1024 + n0) = *(uint4*)o;
}

// ---------------- grouped GEMM ----------------
// PHASE1: 128x256 tile, 256 thr, warp tile 64x64 (8 LDSM : 32 MMA)
// PHASE2: 128x128 tile, 256 thr, warp tile 32x64 (R3 config, 2 CTA/SM)
template<int PHASE>
__global__ __launch_bounds__(256, (PHASE==1)?1:2) void k_gemm(float* __restrict__ out){
    constexpr int KDIM = (PHASE==1) ? D_ : F_;
    constexpr int BN_  = (PHASE==1) ? 256 : 128;
    constexpr int NWM  = (PHASE==1) ? 2 : 4;
    constexpr int MI   = (PHASE==1) ? 4 : 2;
    constexpr int NJ   = 8;
    constexpr int NT   = (PHASE==1) ? (2*F_/BN_) : (D_/BN_);
    constexpr int NK   = KDIM/BK;
    constexpr int CH   = BN_/8;                    // B chunks per row
    constexpr int STG  = 16384 + BN_*BK*2;         // stage bytes

    const int bx = blockIdx.x;
    const int mt = bx & (MT_-1);
    const int rest = bx >> 4;
    const int nt = rest % NT;
    const int e  = rest / NT;
    const int cnt = g_cnt[e];
    const int mstart = mt*128;
    if (mstart >= cnt) return;
    const int rowbase = e*CAP + mstart;

    extern __shared__ __align__(128) char dsm[];
    char* sgen = dsm + ((128 - ((uintptr_t)dsm & 127)) & 127);
    const unsigned sbase = smem_u32(sgen);

    const int tid = threadIdx.x;
    const int lane = tid & 31, warp = tid >> 5;
    const int wm = warp % NWM, wn = warp / NWM;

    const __half* Ap;
    const __half* Bp;
    size_t Bstride;
    if (PHASE==1){
        Ap = g_xg + (size_t)rowbase*KDIM;
        Bp = g_w1h + (size_t)e*D_*8192 + (size_t)nt*BN_;
        Bstride = 8192;
    } else {
        Ap = g_act + (size_t)rowbase*KDIM;
        Bp = g_w2h + (size_t)e*F_*1024 + (size_t)nt*BN_;
        Bstride = 1024;
    }

    auto ld_stage = [&](int st, int k0){
        unsigned a0 = sbase + st*STG;
        unsigned b0 = a0 + 16384;
        #pragma unroll
        for (int it=0; it<4; it++){               // A: 1024 chunks
            int idx = it*256 + tid;
            int r = idx >> 3, u = idx & 7;
            cp16s(a0 + swA(r,u), Ap + (size_t)r*KDIM + k0 + u*8);
        }
        #pragma unroll
        for (int it=0; it<(BK*CH)/256; it++){     // B: 64*CH chunks
            int idx = it*256 + tid;
            int kr = idx / CH, c = idx % CH;
            cp16s(b0 + swB<BN_>(kr,c), Bp + (size_t)(k0+kr)*Bstride + c*8);
        }
    };

    float acc[MI][NJ][4];
    #pragma unroll
    for (int mi=0;mi<MI;mi++)
        #pragma unroll
        for (int nj=0;nj<NJ;nj++)
            #pragma unroll
            for (int v=0;v<4;v++) acc[mi][nj][v] = 0.f;

    ld_stage(0, 0);  cp_commit();
    ld_stage(1, BK); cp_commit();

    #pragma unroll 1
    for (int kt=0; kt<NK; kt++){
        asm volatile("cp.async.wait_group 1;\n");
        __syncthreads();
        if (kt+2 < NK) ld_stage((kt+2)%3, (kt+2)*BK);
        cp_commit();

        const unsigned aS = sbase + (kt%3)*STG;
        const unsigned bS = aS + 16384;

        #pragma unroll
        for (int kk=0; kk<4; kk++){
            const int k0h = kk*16;
            unsigned a[MI][4];
            #pragma unroll
            for (int mi=0;mi<MI;mi++){
                int row = wm*(MI*16) + mi*16 + (lane & 15);
                int chunk = kk*2 + (lane >> 4);
                ldsm4(a[mi][0],a[mi][1],a[mi][2],a[mi][3], aS + swA(row, chunk));
            }
            unsigned b[NJ][2];
            #pragma unroll
            for (int nq=0;nq<NJ/2;nq++){
                int nb = wn*(NJ*8) + nq*16;
                int lr = k0h + (((lane>>4)&1)<<3) + (lane & 7);
                int lc = nb + (((lane>>3)&1)<<3);
                unsigned r0,r1,r2,r3;
                ldsm4t(r0,r1,r2,r3, bS + swB<BN_>(lr, lc>>3));
                b[2*nq  ][0]=r0; b[2*nq  ][1]=r2;
                b[2*nq+1][0]=r1; b[2*nq+1][1]=r3;
            }
            #pragma unroll
            for (int mi=0;mi<MI;mi++)
                #pragma unroll
                for (int nj=0;nj<NJ;nj++)
                    mma16816(acc[mi][nj], a[mi][0],a[mi][1],a[mi][2],a[mi][3], b[nj][0],b[nj][1]);
        }
    }
    __syncthreads();

    if (PHASE==1){
        // fused SiLU(gate)*up; interleaved col pairs in-thread. BN=256 -> 128 act cols.
        __half* stage = (__half*)sgen;            // 128 x 136 halves
        #pragma unroll
        for (int mi=0;mi<MI;mi++){
            #pragma unroll
            for (int nj=0;nj<NJ;nj++){
                int r0 = wm*(MI*16) + mi*16 + (lane>>2);
                int c  = wn*32 + nj*4 + (lane&3);
                float g0=acc[mi][nj][0], u0=acc[mi][nj][1];
                float g1=acc[mi][nj][2], u1=acc[mi][nj][3];
                float a0 = g0/(1.f+__expf(-g0))*u0;
                float a1 = g1/(1.f+__expf(-g1))*u1;
                stage[r0*136 + c]     = __float2half(a0);
                stage[(r0+8)*136 + c] = __float2half(a1);
            }
        }
        __syncthreads();
        __half* dst = g_act + (size_t)rowbase*F_ + (size_t)nt*128;
        #pragma unroll
        for (int it=0; it<8; it++){               // 128 x 128 halves
            int idx = it*256 + tid;
            int r = idx >> 4, cc = (idx & 15) << 3;
            *(uint4*)(dst + (size_t)r*F_ + cc) = *(uint4*)(stage + r*136 + cc);
        }
    } else {
        #pragma unroll
        for (int mi=0;mi<MI;mi++){
            #pragma unroll
            for (int h=0;h<2;h++){
                int r = wm*(MI*16) + mi*16 + (lane>>2) + h*8;
                int srow = mstart + r;
                if (srow >= cnt) continue;
                int slot = e*CAP + srow;
                int tok = g_tok[slot];
                float cf = g_coef[slot];
                float* op = out + (size_t)tok*D_ + (size_t)nt*BN_;
                #pragma unroll
                for (int nj=0;nj<NJ;nj++){
                    int c = wn*64 + nj*8 + ((lane&3)<<1);
                    atomicAdd(op + c,     cf*acc[mi][nj][h*2+0]);
                    atomicAdd(op + c + 1, cf*acc[mi][nj][h*2+1]);
                }
            }
        }
    }
}

#define SMEM1 (3*(16384+256*BK*2) + 128)
#define SMEM2 (3*(16384+128*BK*2) + 128)

// ---------------- launch ----------------
extern "C" void kernel_launch(void* const* d_in, const int* in_sizes, int n_in,
                              void* d_out, int out_size){
    const float* x      = (const float*)d_in[0];
    const float* gating = (const float*)d_in[1];
    const int*   w1q    = (const int*)d_in[2];
    const int*   w2q    = (const int*)d_in[3];
    const float* w1s    = (const float*)d_in[4];
    const float* w2s    = (const float*)d_in[5];
    float* out = (float*)d_out;

    static cudaStream_t s2 = nullptr;
    static cudaEvent_t ef, ej2;
    if (!s2){
        cudaFuncSetAttribute(k_gemm<1>, cudaFuncAttributeMaxDynamicSharedMemorySize, SMEM1);
        cudaFuncSetAttribute(k_gemm<2>, cudaFuncAttributeMaxDynamicSharedMemorySize, SMEM2);
        cudaStreamCreateWithFlags(&s2, cudaStreamNonBlocking);
        cudaEventCreateWithFlags(&ef,  cudaEventDisableTiming);
        cudaEventCreateWithFlags(&ej2, cudaEventDisableTiming);
    }

    // fork point (event records are not kernel launches; ncu numbering unaffected)
    cudaEventRecord(ef, 0);
    cudaStreamWaitEvent(s2, ef, 0);

    // launch-call order chosen so GEMM1 is launch #6 (ncu -s 5 -c 1 captures it)
    k_dq1      <<<32768, 256>>>(w1q, w1s);          // #1 (also zeroes g_cnt)
    k_route    <<<16,    256>>>(gating);            // #2
    k_gatherpad<<<T_+64, 128>>>(x);                 // #3
    k_dq2      <<<16384, 256, 0, s2>>>(w2q, w2s);   // #4 (overlaps #1..#6)
    k_zero     <<<4096,  256, 0, s2>>>(out);        // #5
    cudaEventRecord(ej2, s2);
    k_gemm<1>  <<<E_*32*MT_, 256, SMEM1>>>(out);    // #6  <-- ncu target
    cudaStreamWaitEvent(0, ej2, 0);
    k_gemm<2>  <<<E_*8*MT_,  256, SMEM2>>>(out);    // #7
}

// round 7
// speedup vs baseline: 1.1204x; 1.1204x over previous
#include <cuda_runtime.h>
#include <cuda_fp16.h>
#include <cstdint>

#define E_ 8
#define T_ 4096
#define D_ 1024
#define F_ 4096
#define CAP 2048
#define NSLOT (E_*CAP)
#define MT_ 16

#define BM 128
#define BN 128
#define BK 64
#define STAGES 3
#define STAGE_BYTES 32768
#define SMEM_BYTES (STAGES*STAGE_BYTES + 128)

// ---------------- static scratch ----------------
__device__ __align__(16) __half g_w1h[(size_t)E_*D_*2*F_];   // [e][k][2j+u] gate/up interleaved
__device__ __align__(16) __half g_w2h[(size_t)E_*F_*D_];     // [e][k][n]
__device__ __align__(16) __half g_xg [(size_t)NSLOT*D_];     // gathered x (fp16)
__device__ __align__(16) __half g_act[(size_t)NSLOT*F_];     // intermediate act
__device__ int   g_cnt[E_];
__device__ int   g_tok[NSLOT];
__device__ float g_coef[NSLOT];
__device__ int   g_slot[2*T_];

// ---------------- helpers ----------------
__device__ __forceinline__ unsigned smem_u32(const void* p){
    return (unsigned)__cvta_generic_to_shared(p);
}
__device__ __forceinline__ void cp16s(unsigned s, const void* g){
    asm volatile("cp.async.cg.shared.global [%0], [%1], 16;\n" :: "r"(s), "l"(g));
}
__device__ __forceinline__ void cp16s_ca(unsigned s, const void* g){
    asm volatile("cp.async.ca.shared.global [%0], [%1], 16;\n" :: "r"(s), "l"(g));
}
__device__ __forceinline__ void cp_commit(){ asm volatile("cp.async.commit_group;\n"); }

__device__ __forceinline__ void ldsm4(unsigned&r0,unsigned&r1,unsigned&r2,unsigned&r3,unsigned a){
    asm volatile("ldmatrix.sync.aligned.m8n8.x4.shared.b16 {%0,%1,%2,%3}, [%4];\n"
        : "=r"(r0),"=r"(r1),"=r"(r2),"=r"(r3) : "r"(a));
}
__device__ __forceinline__ void ldsm4t(unsigned&r0,unsigned&r1,unsigned&r2,unsigned&r3,unsigned a){
    asm volatile("ldmatrix.sync.aligned.m8n8.x4.trans.shared.b16 {%0,%1,%2,%3}, [%4];\n"
        : "=r"(r0),"=r"(r1),"=r"(r2),"=r"(r3) : "r"(a));
}
__device__ __forceinline__ void mma16816(float* c, unsigned a0,unsigned a1,unsigned a2,unsigned a3,
                                         unsigned b0,unsigned b1){
    asm volatile("mma.sync.aligned.m16n8k16.row.col.f32.f16.f16.f32 "
        "{%0,%1,%2,%3},{%4,%5,%6,%7},{%8,%9},{%0,%1,%2,%3};\n"
        : "+f"(c[0]),"+f"(c[1]),"+f"(c[2]),"+f"(c[3])
        : "r"(a0),"r"(a1),"r"(a2),"r"(a3),"r"(b0),"r"(b1));
}

// swizzled smem offsets (conflict-free for cp.async 16B stores and ldmatrix)
__device__ __forceinline__ unsigned swA(int r, int c){   // A: 128 x 64 halves, c in [0,8)
    return (unsigned)(r*128 + ((c ^ (r & 7)) << 4));
}
__device__ __forceinline__ unsigned swB(int r, int c){   // B: 64 x 128 halves, c in [0,16)
    return (unsigned)(r*256 + ((c >> 3) << 7) + (((c & 7) ^ (r & 7)) << 4));
}

// ---------------- zero output ----------------
__global__ void k_zero(float* __restrict__ out){
    int i = blockIdx.x*blockDim.x + threadIdx.x;
    float4 z = {0.f,0.f,0.f,0.f};
    ((float4*)out)[i] = z;
}

// ---------------- routing (softmax top-2, renormalized) ----------------
__global__ void k_route(const float* __restrict__ gate){
    int t = blockIdx.x*blockDim.x + threadIdx.x;
    if (t >= T_) return;
    float g[E_];
    #pragma unroll
    for (int i=0;i<E_;i++) g[i] = gate[t*E_+i];
    int i1 = 0; float m1 = g[0];
    #pragma unroll
    for (int i=1;i<E_;i++) if (g[i] > m1){ m1 = g[i]; i1 = i; }
    int i2 = -1; float m2 = -1e30f;
    #pragma unroll
    for (int i=0;i<E_;i++){ if (i==i1) continue; if (g[i] > m2){ m2 = g[i]; i2 = i; } }
    float e2 = expf(m2 - m1);
    float w1 = 1.0f/(1.0f + e2);
    float w2 = e2*w1;
    int p1 = atomicAdd(&g_cnt[i1], 1);
    int s1 = i1*CAP + p1;
    g_tok[s1] = t; g_coef[s1] = w1; g_slot[2*t] = s1;
    int p2 = atomicAdd(&g_cnt[i2], 1);
    int s2 = i2*CAP + p2;
    g_tok[s2] = t; g_coef[s2] = w2; g_slot[2*t+1] = s2;
}

// ---------------- gather x rows + zero-pad, fused ----------------
__global__ void k_gatherpad(const float* __restrict__ x){
    int b = blockIdx.x;
    int tid = threadIdx.x;
    if (b < T_){
        int t = b;
        int s1 = g_slot[2*t], s2 = g_slot[2*t+1];
        const float4* src = (const float4*)(x + (size_t)t*D_);
        __half2* d1 = (__half2*)(g_xg + (size_t)s1*D_);
        __half2* d2 = (__half2*)(g_xg + (size_t)s2*D_);
        float4 a = src[tid*2], c = src[tid*2+1];
        __half2 h0 = __floats2half2_rn(a.x, a.y);
        __half2 h1 = __floats2half2_rn(a.z, a.w);
        __half2 h2 = __floats2half2_rn(c.x, c.y);
        __half2 h3 = __floats2half2_rn(c.z, c.w);
        d1[tid*4+0]=h0; d1[tid*4+1]=h1; d1[tid*4+2]=h2; d1[tid*4+3]=h3;
        d2[tid*4+0]=h0; d2[tid*4+1]=h1; d2[tid*4+2]=h2; d2[tid*4+3]=h3;
    } else {
        int p = b - T_;            // 8 blocks per expert
        int e = p >> 3, sub = p & 7;
        int cnt = g_cnt[e];
        int end = (cnt + 127) & ~127;
        int n2 = (end - cnt)*D_/2;
        __half2* pp = (__half2*)(g_xg + ((size_t)e*CAP + cnt)*D_);
        __half2 z = __float2half2_rn(0.f);
        for (int i = sub*128 + tid; i < n2; i += 1024) pp[i] = z;
    }
}

// ---------------- dequant w1 (interleave gate/up) + zero expert counts ----------------
__global__ void k_dq1(const int* __restrict__ q, const float* __restrict__ s){
    if (blockIdx.x == 0 && threadIdx.x < E_) g_cnt[threadIdx.x] = 0;
    size_t gid = (size_t)blockIdx.x*blockDim.x + threadIdx.x;  // 8388608
    int c8 = (int)(gid & 1023);
    size_t kl = gid >> 10;                 // e*1024 + k
    int k = (int)(kl & 1023); int e = (int)(kl >> 10);
    int j0 = c8*4;
    const int4 gq = *(const int4*)(q + kl*8192 + j0);
    const int4 uq = *(const int4*)(q + kl*8192 + 4096 + j0);
    size_t sb = ((size_t)e*8 + (k>>7))*8192;
    const float4 sg = *(const float4*)(s + sb + j0);
    const float4 su = *(const float4*)(s + sb + 4096 + j0);
    __half2 o[4];
    o[0] = __floats2half2_rn((gq.x-8)*sg.x, (uq.x-8)*su.x);
    o[1] = __floats2half2_rn((gq.y-8)*sg.y, (uq.y-8)*su.y);
    o[2] = __floats2half2_rn((gq.z-8)*sg.z, (uq.z-8)*su.z);
    o[3] = __floats2half2_rn((gq.w-8)*sg.w, (uq.w-8)*su.w);
    *(uint4*)(g_w1h + kl*8192 + (size_t)c8*8) = *(uint4*)o;
}

// ---------------- dequant w2 ----------------
__global__ void k_dq2(const int* __restrict__ q, const float* __restrict__ s){
    size_t gid = (size_t)blockIdx.x*blockDim.x + threadIdx.x;  // 4194304
    int n8 = (int)(gid & 127);
    size_t kl = gid >> 7;                  // e*4096 + k
    int k = (int)(kl & 4095); int e = (int)(kl >> 12);
    int n0 = n8*8;
    const int4 qa = *(const int4*)(q + kl*1024 + n0);
    const int4 qb = *(const int4*)(q + kl*1024 + n0 + 4);
    size_t sbase = ((size_t)e*32 + (k>>7))*1024;
    const float4 sa = *(const float4*)(s + sbase + n0);
    const float4 sb = *(const float4*)(s + sbase + n0 + 4);
    __half2 o[4];
    o[0] = __floats2half2_rn((qa.x-8)*sa.x, (qa.y-8)*sa.y);
    o[1] = __floats2half2_rn((qa.z-8)*sa.z, (qa.w-8)*sa.w);
    o[2] = __floats2half2_rn((qb.x-8)*sb.x, (qb.y-8)*sb.y);
    o[3] = __floats2half2_rn((qb.z-8)*sb.z, (qb.w-8)*sb.w);
    *(uint4*)(g_w2h + kl*1024 + n0) = *(uint4*)o;
}

// ---------------- grouped GEMM: R3-proven config (128x128, 3-stage, 2 CTA/SM) ----------------
template<int PHASE>
__global__ __launch_bounds__(256,2) void k_gemm(float* __restrict__ out){
    constexpr int KDIM = (PHASE==1) ? D_ : F_;
    constexpr int NT   = (PHASE==1) ? (2*F_/BN) : (D_/BN);
    constexpr int NK   = KDIM/BK;

    const int bx = blockIdx.x;
    const int mt = bx & (MT_-1);
    const int rest = bx >> 4;
    const int nt = rest % NT;
    const int e  = rest / NT;
    const int cnt = g_cnt[e];
    const int mstart = mt*BM;
    if (mstart >= cnt) return;
    const int rowbase = e*CAP + mstart;

    extern __shared__ __align__(128) char dsm[];
    char* sgen = dsm + ((128 - ((uintptr_t)dsm & 127)) & 127);
    const unsigned sbase = smem_u32(sgen);

    const int tid = threadIdx.x;
    const int lane = tid & 31, warp = tid >> 5;
    const int wm = warp & 3, wn = warp >> 2;

    const __half* Ap;
    const __half* Bp;
    size_t Bstride;
    if (PHASE==1){
        Ap = g_xg + (size_t)rowbase*KDIM;
        Bp = g_w1h + (size_t)e*D_*8192 + (size_t)nt*BN;
        Bstride = 8192;
    } else {
        Ap = g_act + (size_t)rowbase*KDIM;
        Bp = g_w2h + (size_t)e*F_*1024 + (size_t)nt*BN;
        Bstride = 1024;
    }

    auto ld_stage = [&](int st, int k0){
        unsigned a0 = sbase + st*STAGE_BYTES;
        unsigned b0 = a0 + 16384;
        #pragma unroll
        for (int it=0; it<4; it++){          // A: 128 x 64 halves
            int idx = it*256 + tid;
            int r = idx >> 3, u = idx & 7;
            cp16s(a0 + swA(r,u), Ap + (size_t)r*KDIM + k0 + u*8);
        }
        #pragma unroll
        for (int it=0; it<4; it++){          // B: 64 x 128 halves (L1-cached: cross-CTA reuse)
            int idx = it*256 + tid;
            int kr = idx >> 4, c = idx & 15;
            cp16s_ca(b0 + swB(kr,c), Bp + (size_t)(k0+kr)*Bstride + c*8);
        }
    };

    float acc[2][8][4];
    #pragma unroll
    for (int mi=0;mi<2;mi++)
        #pragma unroll
        for (int nj=0;nj<8;nj++)
            #pragma unroll
            for (int v=0;v<4;v++) acc[mi][nj][v] = 0.f;

    ld_stage(0, 0);  cp_commit();
    ld_stage(1, BK); cp_commit();

    #pragma unroll 1
    for (int kt=0; kt<NK; kt++){
        asm volatile("cp.async.wait_group 1;\n");
        __syncthreads();
        if (kt+2 < NK) ld_stage((kt+2)%STAGES, (kt+2)*BK);
        cp_commit();

        const int cur = kt % STAGES;
        const unsigned aS = sbase + cur*STAGE_BYTES;
        const unsigned bS = aS + 16384;

        #pragma unroll
        for (int kk=0; kk<4; kk++){
            const int k0h = kk*16;
            unsigned a[2][4];
            #pragma unroll
            for (int mi=0;mi<2;mi++){
                int row = wm*32 + mi*16 + (lane & 15);
                int chunk = kk*2 + (lane >> 4);
                ldsm4(a[mi][0],a[mi][1],a[mi][2],a[mi][3], aS + swA(row, chunk));
            }
            unsigned b[8][2];
            #pragma unroll
            for (int nq=0;nq<4;nq++){
                int nb = wn*64 + nq*16;
                int lr = k0h + (((lane>>4)&1)<<3) + (lane & 7);
                int lc = nb + (((lane>>3)&1)<<3);
                unsigned r0,r1,r2,r3;
                ldsm4t(r0,r1,r2,r3, bS + swB(lr, lc>>3));
                b[2*nq  ][0]=r0; b[2*nq  ][1]=r2;
                b[2*nq+1][0]=r1; b[2*nq+1][1]=r3;
            }
            #pragma unroll
            for (int mi=0;mi<2;mi++)
                #pragma unroll
                for (int nj=0;nj<8;nj++)
                    mma16816(acc[mi][nj], a[mi][0],a[mi][1],a[mi][2],a[mi][3], b[nj][0],b[nj][1]);
        }
    }
    __syncthreads();

    if (PHASE==1){
        // fused SiLU(gate)*up: interleaved column pairs live in the same thread
        __half* stage = (__half*)sgen;       // 128 x 72 halves
        #pragma unroll
        for (int mi=0;mi<2;mi++){
            #pragma unroll
            for (int nj=0;nj<8;nj++){
                int r0 = wm*32 + mi*16 + (lane>>2);
                int c  = wn*32 + nj*4 + (lane&3);
                float g0=acc[mi][nj][0], u0=acc[mi][nj][1];
                float g1=acc[mi][nj][2], u1=acc[mi][nj][3];
                float a0 = g0/(1.f+__expf(-g0))*u0;
                float a1 = g1/(1.f+__expf(-g1))*u1;
                stage[r0*72 + c]     = __float2half(a0);
                stage[(r0+8)*72 + c] = __float2half(a1);
            }
        }
        __syncthreads();
        __half* dst = g_act + (size_t)rowbase*F_ + (size_t)nt*64;
        #pragma unroll
        for (int it=0; it<4; it++){
            int idx = it*256 + tid;
            int r = idx >> 3, cc = (idx & 7) << 3;
            *(uint4*)(dst + (size_t)r*F_ + cc) = *(uint4*)(stage + r*72 + cc);
        }
    } else {
        #pragma unroll
        for (int mi=0;mi<2;mi++){
            #pragma unroll
            for (int h=0;h<2;h++){
                int r = wm*32 + mi*16 + (lane>>2) + h*8;
                int srow = mstart + r;
                if (srow >= cnt) continue;
                int slot = e*CAP + srow;
                int tok = g_tok[slot];
                float cf = g_coef[slot];
                float* op = out + (size_t)tok*D_ + (size_t)nt*BN;
                #pragma unroll
                for (int nj=0;nj<8;nj++){
                    int c = wn*64 + nj*8 + ((lane&3)<<1);
                    atomicAdd(op + c,     cf*acc[mi][nj][h*2+0]);
                    atomicAdd(op + c + 1, cf*acc[mi][nj][h*2+1]);
                }
            }
        }
    }
}

// ---------------- launch ----------------
// Submission order puts k_gemm<1> as our 4th launch (harness issues 2 first;
// ncu -s 5 -c 1 then captures it). dq2+zero run on a side stream DURING gemm1.
extern "C" void kernel_launch(void* const* d_in, const int* in_sizes, int n_in,
                              void* d_out, int out_size){
    const float* x      = (const float*)d_in[0];
    const float* gating = (const float*)d_in[1];
    const int*   w1q    = (const int*)d_in[2];
    const int*   w2q    = (const int*)d_in[3];
    const float* w1s    = (const float*)d_in[4];
    const float* w2s    = (const float*)d_in[5];
    float* out = (float*)d_out;

    static cudaStream_t s2 = nullptr;
    static cudaEvent_t e1, ej2;
    if (!s2){
        cudaFuncSetAttribute(k_gemm<1>, cudaFuncAttributeMaxDynamicSharedMemorySize, SMEM_BYTES);
        cudaFuncSetAttribute(k_gemm<2>, cudaFuncAttributeMaxDynamicSharedMemorySize, SMEM_BYTES);
        cudaStreamCreateWithFlags(&s2, cudaStreamNonBlocking);
        cudaEventCreateWithFlags(&e1,  cudaEventDisableTiming);
        cudaEventCreateWithFlags(&ej2, cudaEventDisableTiming);
    }

    k_dq1      <<<32768, 256>>>(w1q, w1s);          // launch 1 (also zeroes g_cnt)
    cudaEventRecord(e1, 0);
    k_route    <<<16,    256>>>(gating);            // launch 2
    k_gatherpad<<<T_+64, 128>>>(x);                 // launch 3
    k_gemm<1>  <<<E_*64*MT_, 256, SMEM_BYTES>>>(out);  // launch 4 <-- ncu target

    // side stream: dq2 + zero execute concurrently with gemm1 (after dq1 drains)
    cudaStreamWaitEvent(s2, e1, 0);
    k_dq2      <<<16384, 256, 0, s2>>>(w2q, w2s);   // launch 5
    k_zero     <<<4096,  256, 0, s2>>>(out);        // launch 6
    cudaEventRecord(ej2, s2);

    cudaStreamWaitEvent(0, ej2, 0);
    k_gemm<2>  <<<E_*8*MT_,  256, SMEM_BYTES>>>(out);  // launch 7
}

// round 8
// speedup vs baseline: 1.1917x; 1.0637x over previous
#include <cuda_runtime.h>
#include <cuda.h>
#include <cuda_fp16.h>
#include <cstdint>

#define E_ 8
#define T_ 4096
#define D_ 1024
#define F_ 4096
#define CAP 2048
#define NSLOT (E_*CAP)
#define MT_ 16

#define BM 128
#define BN 128
#define BK 64
#define STAGES 3
#define STAGE_BYTES 32768
#define MBAR_OFF (STAGES*STAGE_BYTES)          // 98304
#define SMEM_BYTES (MBAR_OFF + 1088)           // stages + barriers + align slack

// ---------------- static scratch ----------------
__device__ __align__(16) __half g_w1h[(size_t)E_*D_*2*F_];   // [e][k][2j+u] gate/up interleaved
__device__ __align__(16) __half g_w2h[(size_t)E_*F_*D_];     // [e][k][n]
__device__ __align__(16) __half g_xg [(size_t)NSLOT*D_];     // gathered x (fp16)
__device__ __align__(16) __half g_act[(size_t)NSLOT*F_];     // intermediate act
__device__ int   g_cnt[E_];
__device__ int   g_tok[NSLOT];
__device__ float g_coef[NSLOT];
__device__ int   g_slot[2*T_];

// ---------------- helpers ----------------
__device__ __forceinline__ unsigned smem_u32(const void* p){
    return (unsigned)__cvta_generic_to_shared(p);
}
__device__ __forceinline__ void mbar_init(unsigned a, unsigned cnt){
    asm volatile("mbarrier.init.shared.b64 [%0], %1;" :: "r"(a), "r"(cnt) : "memory");
}
__device__ __forceinline__ void mbar_expect(unsigned a, unsigned bytes){
    asm volatile("mbarrier.arrive.expect_tx.shared.b64 _, [%0], %1;" :: "r"(a), "r"(bytes) : "memory");
}
__device__ __forceinline__ void mbar_wait(unsigned a, unsigned par){
    asm volatile("{\n.reg .pred P1;\nLW_%=:\nmbarrier.try_wait.parity.acquire.cta.shared::cta.b64 P1, [%0], %1, 0x989680;\n@P1 bra LD_%=;\nbra LW_%=;\nLD_%=:\n}"
        :: "r"(a), "r"(par) : "memory");
}
__device__ __forceinline__ void tma2d(unsigned dst, const CUtensorMap* m, int x, int y, unsigned bar){
    asm volatile("cp.async.bulk.tensor.2d.shared::cta.global.tile.mbarrier::complete_tx::bytes "
        "[%0], [%1, {%2, %3}], [%4];"
        :: "r"(dst), "l"(m), "r"(x), "r"(y), "r"(bar) : "memory");
}
__device__ __forceinline__ void ldsm4(unsigned&r0,unsigned&r1,unsigned&r2,unsigned&r3,unsigned a){
    asm volatile("ldmatrix.sync.aligned.m8n8.x4.shared.b16 {%0,%1,%2,%3}, [%4];\n"
        : "=r"(r0),"=r"(r1),"=r"(r2),"=r"(r3) : "r"(a));
}
__device__ __forceinline__ void ldsm4t(unsigned&r0,unsigned&r1,unsigned&r2,unsigned&r3,unsigned a){
    asm volatile("ldmatrix.sync.aligned.m8n8.x4.trans.shared.b16 {%0,%1,%2,%3}, [%4];\n"
        : "=r"(r0),"=r"(r1),"=r"(r2),"=r"(r3) : "r"(a));
}
__device__ __forceinline__ void mma16816(float* c, unsigned a0,unsigned a1,unsigned a2,unsigned a3,
                                         unsigned b0,unsigned b1){
    asm volatile("mma.sync.aligned.m16n8k16.row.col.f32.f16.f16.f32 "
        "{%0,%1,%2,%3},{%4,%5,%6,%7},{%8,%9},{%0,%1,%2,%3};\n"
        : "+f"(c[0]),"+f"(c[1]),"+f"(c[2]),"+f"(c[3])
        : "r"(a0),"r"(a1),"r"(a2),"r"(a3),"r"(b0),"r"(b1));
}

// ---------------- zero output ----------------
__global__ void k_zero(float* __restrict__ out){
    int i = blockIdx.x*blockDim.x + threadIdx.x;
    float4 z = {0.f,0.f,0.f,0.f};
    ((float4*)out)[i] = z;
}

// ---------------- routing ----------------
__global__ void k_route(const float* __restrict__ gate){
    int t = blockIdx.x*blockDim.x + threadIdx.x;
    if (t >= T_) return;
    float g[E_];
    #pragma unroll
    for (int i=0;i<E_;i++) g[i] = gate[t*E_+i];
    int i1 = 0; float m1 = g[0];
    #pragma unroll
    for (int i=1;i<E_;i++) if (g[i] > m1){ m1 = g[i]; i1 = i; }
    int i2 = -1; float m2 = -1e30f;
    #pragma unroll
    for (int i=0;i<E_;i++){ if (i==i1) continue; if (g[i] > m2){ m2 = g[i]; i2 = i; } }
    float e2 = expf(m2 - m1);
    float w1 = 1.0f/(1.0f + e2);
    float w2 = e2*w1;
    int p1 = atomicAdd(&g_cnt[i1], 1);
    int s1 = i1*CAP + p1;
    g_tok[s1] = t; g_coef[s1] = w1; g_slot[2*t] = s1;
    int p2 = atomicAdd(&g_cnt[i2], 1);
    int s2 = i2*CAP + p2;
    g_tok[s2] = t; g_coef[s2] = w2; g_slot[2*t+1] = s2;
}

// ---------------- gather x rows + zero-pad, fused ----------------
__global__ void k_gatherpad(const float* __restrict__ x){
    int b = blockIdx.x;
    int tid = threadIdx.x;
    if (b < T_){
        int t = b;
        int s1 = g_slot[2*t], s2 = g_slot[2*t+1];
        const float4* src = (const float4*)(x + (size_t)t*D_);
        __half2* d1 = (__half2*)(g_xg + (size_t)s1*D_);
        __half2* d2 = (__half2*)(g_xg + (size_t)s2*D_);
        float4 a = src[tid*2], c = src[tid*2+1];
        __half2 h0 = __floats2half2_rn(a.x, a.y);
        __half2 h1 = __floats2half2_rn(a.z, a.w);
        __half2 h2 = __floats2half2_rn(c.x, c.y);
        __half2 h3 = __floats2half2_rn(c.z, c.w);
        d1[tid*4+0]=h0; d1[tid*4+1]=h1; d1[tid*4+2]=h2; d1[tid*4+3]=h3;
        d2[tid*4+0]=h0; d2[tid*4+1]=h1; d2[tid*4+2]=h2; d2[tid*4+3]=h3;
    } else {
        int p = b - T_;
        int e = p >> 3, sub = p & 7;
        int cnt = g_cnt[e];
        int end = (cnt + 127) & ~127;
        int n2 = (end - cnt)*D_/2;
        __half2* pp = (__half2*)(g_xg + ((size_t)e*CAP + cnt)*D_);
        __half2 z = __float2half2_rn(0.f);
        for (int i = sub*128 + tid; i < n2; i += 1024) pp[i] = z;
    }
}

// ---------------- dequant w1 (interleave gate/up) + zero expert counts ----------------
__global__ void k_dq1(const int* __restrict__ q, const float* __restrict__ s){
    if (blockIdx.x == 0 && threadIdx.x < E_) g_cnt[threadIdx.x] = 0;
    size_t gid = (size_t)blockIdx.x*blockDim.x + threadIdx.x;
    int c8 = (int)(gid & 1023);
    size_t kl = gid >> 10;
    int k = (int)(kl & 1023); int e = (int)(kl >> 10);
    int j0 = c8*4;
    const int4 gq = *(const int4*)(q + kl*8192 + j0);
    const int4 uq = *(const int4*)(q + kl*8192 + 4096 + j0);
    size_t sb = ((size_t)e*8 + (k>>7))*8192;
    const float4 sg = *(const float4*)(s + sb + j0);
    const float4 su = *(const float4*)(s + sb + 4096 + j0);
    __half2 o[4];
    o[0] = __floats2half2_rn((gq.x-8)*sg.x, (uq.x-8)*su.x);
    o[1] = __floats2half2_rn((gq.y-8)*sg.y, (uq.y-8)*su.y);
    o[2] = __floats2half2_rn((gq.z-8)*sg.z, (uq.z-8)*su.z);
    o[3] = __floats2half2_rn((gq.w-8)*sg.w, (uq.w-8)*su.w);
    *(uint4*)(g_w1h + kl*8192 + (size_t)c8*8) = *(uint4*)o;
}

// ---------------- dequant w2 ----------------
__global__ void k_dq2(const int* __restrict__ q, const float* __restrict__ s){
    size_t gid = (size_t)blockIdx.x*blockDim.x + threadIdx.x;
    int n8 = (int)(gid & 127);
    size_t kl = gid >> 7;
    int k = (int)(kl & 4095); int e = (int)(kl >> 12);
    int n0 = n8*8;
    const int4 qa = *(const int4*)(q + kl*1024 + n0);
    const int4 qb = *(const int4*)(q + kl*1024 + n0 + 4);
    size_t sbase = ((size_t)e*32 + (k>>7))*1024;
    const float4 sa = *(const float4*)(s + sbase + n0);
    const float4 sb = *(const float4*)(s + sbase + n0 + 4);
    __half2 o[4];
    o[0] = __floats2half2_rn((qa.x-8)*sa.x, (qa.y-8)*sa.y);
    o[1] = __floats2half2_rn((qa.z-8)*sa.z, (qa.w-8)*sa.w);
    o[2] = __floats2half2_rn((qb.x-8)*sb.x, (qb.y-8)*sb.y);
    o[3] = __floats2half2_rn((qb.z-8)*sb.z, (qb.w-8)*sb.w);
    *(uint4*)(g_w2h + kl*1024 + n0) = *(uint4*)o;
}

// ---------------- grouped GEMM: TMA + mbarrier 3-stage, 128x128, 2 CTA/SM ----------------
// Stage layout: A [0,16KB) = 128 rows x 128B (SW128); B [16KB,32KB) = two 8KB atoms,
// each 64 k-rows x 128B (SW128), atom b = n-block (n in [64b, 64b+64)).
template<int PHASE>
__global__ __launch_bounds__(256,2) void k_gemm(float* __restrict__ out,
        const __grid_constant__ CUtensorMap mA, const __grid_constant__ CUtensorMap mB){
    constexpr int KDIM = (PHASE==1) ? D_ : F_;
    constexpr int NT   = (PHASE==1) ? (2*F_/BN) : (D_/BN);
    constexpr int NK   = KDIM/BK;

    const int bx = blockIdx.x;
    const int mt = bx & (MT_-1);
    const int rest = bx >> 4;
    const int nt = rest % NT;
    const int e  = rest / NT;
    const int cnt = g_cnt[e];
    const int mstart = mt*BM;
    if (mstart >= cnt) return;
    const int rowbase = e*CAP + mstart;

    extern __shared__ __align__(1024) char dsm[];
    const unsigned sbase = (smem_u32(dsm) + 1023u) & ~1023u;

    const int tid = threadIdx.x;
    const int lane = tid & 31, warp = tid >> 5;
    const int wm = warp & 3, wn = warp >> 2;

    // barriers
    if (tid == 0){
        #pragma unroll
        for (int s=0;s<STAGES;s++) mbar_init(sbase + MBAR_OFF + s*8, 1);
        asm volatile("fence.proxy.async.shared::cta;" ::: "memory");
    }
    __syncthreads();

    auto issue = [&](int st, int k0){
        unsigned aD = sbase + st*STAGE_BYTES;
        unsigned bD = aD + 16384;
        unsigned bar = sbase + MBAR_OFF + st*8;
        mbar_expect(bar, 32768);
        tma2d(aD,        &mA, k0,        rowbase,      bar);
        tma2d(bD,        &mB, nt*BN,     e*KDIM + k0,  bar);
        tma2d(bD + 8192, &mB, nt*BN+64,  e*KDIM + k0,  bar);
    };

    float acc[2][8][4];
    #pragma unroll
    for (int mi=0;mi<2;mi++)
        #pragma unroll
        for (int nj=0;nj<8;nj++)
            #pragma unroll
            for (int v=0;v<4;v++) acc[mi][nj][v] = 0.f;

    if (tid == 0){ issue(0, 0); issue(1, BK); }
    int ph0=0, ph1=0, ph2=0;

    #pragma unroll 1
    for (int kt=0; kt<NK; kt++){
        const int s = kt % STAGES;
        if (tid == 0 && kt+2 < NK) issue((kt+2)%STAGES, (kt+2)*BK);
        // wait for stage data
        {
            unsigned bar = sbase + MBAR_OFF + s*8;
            int par = (s==0)?ph0:((s==1)?ph1:ph2);
            mbar_wait(bar, (unsigned)par);
            if (s==0) ph0^=1; else if (s==1) ph1^=1; else ph2^=1;
        }
        const unsigned aS = sbase + s*STAGE_BYTES;
        const unsigned bS = aS + 16384;

        #pragma unroll
        for (int kk=0; kk<4; kk++){
            const int k0h = kk*16;
            unsigned a[2][4];
            #pragma unroll
            for (int mi=0;mi<2;mi++){
                int row = wm*32 + mi*16 + (lane & 15);
                int chunk = kk*2 + (lane >> 4);
                ldsm4(a[mi][0],a[mi][1],a[mi][2],a[mi][3],
                      aS + row*128 + (((chunk ^ (row & 7))) << 4));
            }
            unsigned b[8][2];
            #pragma unroll
            for (int nq=0;nq<4;nq++){
                int nb = wn*64 + nq*16;
                int lr = k0h + (((lane>>4)&1)<<3) + (lane & 7);
                int lc = nb + (((lane>>3)&1)<<3);
                int blk = lc >> 6;
                int c6  = (lc >> 3) & 7;
                unsigned r0,r1,r2,r3;
                ldsm4t(r0,r1,r2,r3,
                       bS + blk*8192 + lr*128 + ((c6 ^ (lr & 7)) << 4));
                b[2*nq  ][0]=r0; b[2*nq  ][1]=r2;
                b[2*nq+1][0]=r1; b[2*nq+1][1]=r3;
            }
            #pragma unroll
            for (int mi=0;mi<2;mi++)
                #pragma unroll
                for (int nj=0;nj<8;nj++)
                    mma16816(acc[mi][nj], a[mi][0],a[mi][1],a[mi][2],a[mi][3], b[nj][0],b[nj][1]);
        }
        __syncthreads();
    }

    if (PHASE==1){
        // fused SiLU(gate)*up: interleaved column pairs live in the same thread
        __half* stage = (__half*)(dsm + (sbase - smem_u32(dsm)));   // stage 0 region
        #pragma unroll
        for (int mi=0;mi<2;mi++){
            #pragma unroll
            for (int nj=0;nj<8;nj++){
                int r0 = wm*32 + mi*16 + (lane>>2);
                int c  = wn*32 + nj*4 + (lane&3);
                float g0=acc[mi][nj][0], u0=acc[mi][nj][1];
                float g1=acc[mi][nj][2], u1=acc[mi][nj][3];
                float a0 = g0/(1.f+__expf(-g0))*u0;
                float a1 = g1/(1.f+__expf(-g1))*u1;
                stage[r0*72 + c]     = __float2half(a0);
                stage[(r0+8)*72 + c] = __float2half(a1);
            }
        }
        __syncthreads();
        __half* dst = g_act + (size_t)rowbase*F_ + (size_t)nt*64;
        #pragma unroll
        for (int it=0; it<4; it++){
            int idx = it*256 + tid;
            int r = idx >> 3, cc = (idx & 7) << 3;
            *(uint4*)(dst + (size_t)r*F_ + cc) = *(uint4*)(stage + r*72 + cc);
        }
    } else {
        #pragma unroll
        for (int mi=0;mi<2;mi++){
            #pragma unroll
            for (int h=0;h<2;h++){
                int r = wm*32 + mi*16 + (lane>>2) + h*8;
                int srow = mstart + r;
                if (srow >= cnt) continue;
                int slot = e*CAP + srow;
                int tok = g_tok[slot];
                float cf = g_coef[slot];
                float* op = out + (size_t)tok*D_ + (size_t)nt*BN;
                #pragma unroll
                for (int nj=0;nj<8;nj++){
                    int c = wn*64 + nj*8 + ((lane&3)<<1);
                    atomicAdd(op + c,     cf*acc[mi][nj][h*2+0]);
                    atomicAdd(op + c + 1, cf*acc[mi][nj][h*2+1]);
                }
            }
        }
    }
}

// ---------------- host: tensormap setup + launch ----------------
typedef CUresult (CUDAAPI *EncodeFn)(CUtensorMap*, CUtensorMapDataType, cuuint32_t, void*,
    const cuuint64_t*, const cuuint64_t*, const cuuint32_t*, const cuuint32_t*,
    CUtensorMapInterleave, CUtensorMapSwizzle, CUtensorMapL2promotion, CUtensorMapFloatOOBfill);

static void build_map(EncodeFn enc, CUtensorMap* m, void* addr,
                      uint64_t inner, uint64_t outer, uint32_t box_in, uint32_t box_out){
    cuuint64_t dims[2]    = { inner, outer };
    cuuint64_t strides[1] = { inner * 2 };               // bytes, fp16
    cuuint32_t box[2]     = { box_in, box_out };
    cuuint32_t estr[2]    = { 1, 1 };
    enc(m, CU_TENSOR_MAP_DATA_TYPE_UINT16, 2, addr, dims, strides, box, estr,
        CU_TENSOR_MAP_INTERLEAVE_NONE, CU_TENSOR_MAP_SWIZZLE_128B,
        CU_TENSOR_MAP_L2_PROMOTION_L2_128B, CU_TENSOR_MAP_FLOAT_OOB_FILL_NONE);
}

extern "C" void kernel_launch(void* const* d_in, const int* in_sizes, int n_in,
                              void* d_out, int out_size){
    const float* x      = (const float*)d_in[0];
    const float* gating = (const float*)d_in[1];
    const int*   w1q    = (const int*)d_in[2];
    const int*   w2q    = (const int*)d_in[3];
    const float* w1s    = (const float*)d_in[4];
    const float* w2s    = (const float*)d_in[5];
    float* out = (float*)d_out;

    static cudaStream_t s2 = nullptr;
    static cudaEvent_t e1, ej2;
    static CUtensorMap mXg, mAct, mW1, mW2;
    if (!s2){
        cudaFuncSetAttribute(k_gemm<1>, cudaFuncAttributeMaxDynamicSharedMemorySize, SMEM_BYTES);
        cudaFuncSetAttribute(k_gemm<2>, cudaFuncAttributeMaxDynamicSharedMemorySize, SMEM_BYTES);
        cudaStreamCreateWithFlags(&s2, cudaStreamNonBlocking);
        cudaEventCreateWithFlags(&e1,  cudaEventDisableTiming);
        cudaEventCreateWithFlags(&ej2, cudaEventDisableTiming);

        EncodeFn enc = nullptr;
        cudaDriverEntryPointQueryResult qr;
        cudaGetDriverEntryPoint("cuTensorMapEncodeTiled", (void**)&enc, cudaEnableDefault, &qr);
        void *pXg, *pAct, *pW1, *pW2;
        cudaGetSymbolAddress(&pXg,  g_xg);
        cudaGetSymbolAddress(&pAct, g_act);
        cudaGetSymbolAddress(&pW1,  g_w1h);
        cudaGetSymbolAddress(&pW2,  g_w2h);
        build_map(enc, &mXg,  pXg,  D_,    NSLOT,       64, 128);  // A for GEMM1
        build_map(enc, &mAct, pAct, F_,    NSLOT,       64, 128);  // A for GEMM2
        build_map(enc, &mW1,  pW1,  2*F_,  (uint64_t)E_*D_, 64, 64);   // B for GEMM1
        build_map(enc, &mW2,  pW2,  D_,    (uint64_t)E_*F_, 64, 64);   // B for GEMM2
    }

    k_dq1      <<<32768, 256>>>(w1q, w1s);             // launch 1 (also zeroes g_cnt)
    cudaEventRecord(e1, 0);
    k_route    <<<16,    256>>>(gating);               // launch 2
    k_gatherpad<<<T_+64, 128>>>(x);                    // launch 3
    k_gemm<1>  <<<E_*64*MT_, 256, SMEM_BYTES>>>(out, mXg, mW1);   // launch 4 <-- ncu target

    cudaStreamWaitEvent(s2, e1, 0);
    k_dq2      <<<16384, 256, 0, s2>>>(w2q, w2s);      // launch 5 (overlaps gemm1)
    k_zero     <<<4096,  256, 0, s2>>>(out);           // launch 6
    cudaEventRecord(ej2, s2);

    cudaStreamWaitEvent(0, ej2, 0);
    k_gemm<2>  <<<E_*8*MT_,  256, SMEM_BYTES>>>(out, mAct, mW2);  // launch 7
}

// round 9
// speedup vs baseline: 1.2399x; 1.0404x over previous
#include <cuda_runtime.h>
#include <cuda.h>
#include <cuda_fp16.h>
#include <cstdint>

#define E_ 8
#define T_ 4096
#define D_ 1024
#define F_ 4096
#define CAP 2048
#define NSLOT (E_*CAP)
#define MT_ 16

#define BM 128
#define BN 128
#define BK 64
#define STAGES 3
#define STAGE_BYTES 32768
#define MBAR_OFF (STAGES*STAGE_BYTES)
#define SMEM_BYTES (MBAR_OFF + 1088)

// ---------------- static scratch ----------------
__device__ __align__(16) __half g_w1h[(size_t)E_*D_*2*F_];   // [e][k][2j+u] gate/up interleaved
__device__ __align__(16) __half g_w2h[(size_t)E_*F_*D_];     // [e][k][n]
__device__ __align__(16) __half g_xg [(size_t)NSLOT*D_];     // gathered x (fp16)
__device__ __align__(16) __half g_act[(size_t)NSLOT*F_];     // intermediate act
__device__ int   g_cnt[E_];
__device__ int   g_tok[NSLOT];
__device__ float g_coef[NSLOT];
__device__ int   g_slot[2*T_];

// ---------------- helpers ----------------
__device__ __forceinline__ unsigned smem_u32(const void* p){
    return (unsigned)__cvta_generic_to_shared(p);
}
__device__ __forceinline__ void mbar_init(unsigned a, unsigned cnt){
    asm volatile("mbarrier.init.shared.b64 [%0], %1;" :: "r"(a), "r"(cnt) : "memory");
}
__device__ __forceinline__ void mbar_expect(unsigned a, unsigned bytes){
    asm volatile("mbarrier.arrive.expect_tx.shared.b64 _, [%0], %1;" :: "r"(a), "r"(bytes) : "memory");
}
__device__ __forceinline__ void mbar_wait(unsigned a, unsigned par){
    asm volatile("{\n.reg .pred P1;\nLW_%=:\nmbarrier.try_wait.parity.acquire.cta.shared::cta.b64 P1, [%0], %1, 0x989680;\n@P1 bra LD_%=;\nbra LW_%=;\nLD_%=:\n}"
        :: "r"(a), "r"(par) : "memory");
}
__device__ __forceinline__ void tma2d(unsigned dst, const CUtensorMap* m, int x, int y, unsigned bar){
    asm volatile("cp.async.bulk.tensor.2d.shared::cta.global.tile.mbarrier::complete_tx::bytes "
        "[%0], [%1, {%2, %3}], [%4];"
        :: "r"(dst), "l"(m), "r"(x), "r"(y), "r"(bar) : "memory");
}
__device__ __forceinline__ void ldsm4(unsigned&r0,unsigned&r1,unsigned&r2,unsigned&r3,unsigned a){
    asm volatile("ldmatrix.sync.aligned.m8n8.x4.shared.b16 {%0,%1,%2,%3}, [%4];\n"
        : "=r"(r0),"=r"(r1),"=r"(r2),"=r"(r3) : "r"(a));
}
__device__ __forceinline__ void ldsm4t(unsigned&r0,unsigned&r1,unsigned&r2,unsigned&r3,unsigned a){
    asm volatile("ldmatrix.sync.aligned.m8n8.x4.trans.shared.b16 {%0,%1,%2,%3}, [%4];\n"
        : "=r"(r0),"=r"(r1),"=r"(r2),"=r"(r3) : "r"(a));
}
__device__ __forceinline__ void mma16816(float* c, unsigned a0,unsigned a1,unsigned a2,unsigned a3,
                                         unsigned b0,unsigned b1){
    asm volatile("mma.sync.aligned.m16n8k16.row.col.f32.f16.f16.f32 "
        "{%0,%1,%2,%3},{%4,%5,%6,%7},{%8,%9},{%0,%1,%2,%3};\n"
        : "+f"(c[0]),"+f"(c[1]),"+f"(c[2]),"+f"(c[3])
        : "r"(a0),"r"(a1),"r"(a2),"r"(a3),"r"(b0),"r"(b1));
}

// ---------------- zero output ----------------
__global__ void k_zero(float* __restrict__ out){
    int i = blockIdx.x*blockDim.x + threadIdx.x;
    float4 z = {0.f,0.f,0.f,0.f};
    ((float4*)out)[i] = z;
}

// ---------------- routing ----------------
__global__ void k_route(const float* __restrict__ gate){
    int t = blockIdx.x*blockDim.x + threadIdx.x;
    if (t >= T_) return;
    float g[E_];
    #pragma unroll
    for (int i=0;i<E_;i++) g[i] = gate[t*E_+i];
    int i1 = 0; float m1 = g[0];
    #pragma unroll
    for (int i=1;i<E_;i++) if (g[i] > m1){ m1 = g[i]; i1 = i; }
    int i2 = -1; float m2 = -1e30f;
    #pragma unroll
    for (int i=0;i<E_;i++){ if (i==i1) continue; if (g[i] > m2){ m2 = g[i]; i2 = i; } }
    float e2 = expf(m2 - m1);
    float w1 = 1.0f/(1.0f + e2);
    float w2 = e2*w1;
    int p1 = atomicAdd(&g_cnt[i1], 1);
    int s1 = i1*CAP + p1;
    g_tok[s1] = t; g_coef[s1] = w1; g_slot[2*t] = s1;
    int p2 = atomicAdd(&g_cnt[i2], 1);
    int s2 = i2*CAP + p2;
    g_tok[s2] = t; g_coef[s2] = w2; g_slot[2*t+1] = s2;
}

// ---------------- gather x rows + zero-pad, fused ----------------
__global__ void k_gatherpad(const float* __restrict__ x){
    int b = blockIdx.x;
    int tid = threadIdx.x;
    if (b < T_){
        int t = b;
        int s1 = g_slot[2*t], s2 = g_slot[2*t+1];
        const float4* src = (const float4*)(x + (size_t)t*D_);
        __half2* d1 = (__half2*)(g_xg + (size_t)s1*D_);
        __half2* d2 = (__half2*)(g_xg + (size_t)s2*D_);
        float4 a = src[tid*2], c = src[tid*2+1];
        __half2 h0 = __floats2half2_rn(a.x, a.y);
        __half2 h1 = __floats2half2_rn(a.z, a.w);
        __half2 h2 = __floats2half2_rn(c.x, c.y);
        __half2 h3 = __floats2half2_rn(c.z, c.w);
        d1[tid*4+0]=h0; d1[tid*4+1]=h1; d1[tid*4+2]=h2; d1[tid*4+3]=h3;
        d2[tid*4+0]=h0; d2[tid*4+1]=h1; d2[tid*4+2]=h2; d2[tid*4+3]=h3;
    } else {
        int p = b - T_;
        int e = p >> 3, sub = p & 7;
        int cnt = g_cnt[e];
        int end = (cnt + 127) & ~127;
        int n2 = (end - cnt)*D_/2;
        __half2* pp = (__half2*)(g_xg + ((size_t)e*CAP + cnt)*D_);
        __half2 z = __float2half2_rn(0.f);
        for (int i = sub*128 + tid; i < n2; i += 1024) pp[i] = z;
    }
}

// ---------------- dequant w1 (interleave gate/up) + zero expert counts ----------------
__global__ void k_dq1(const int* __restrict__ q, const float* __restrict__ s){
    if (blockIdx.x == 0 && threadIdx.x < E_) g_cnt[threadIdx.x] = 0;
    size_t gid = (size_t)blockIdx.x*blockDim.x + threadIdx.x;
    int c8 = (int)(gid & 1023);
    size_t kl = gid >> 10;
    int k = (int)(kl & 1023); int e = (int)(kl >> 10);
    int j0 = c8*4;
    const int4 gq = *(const int4*)(q + kl*8192 + j0);
    const int4 uq = *(const int4*)(q + kl*8192 + 4096 + j0);
    size_t sb = ((size_t)e*8 + (k>>7))*8192;
    const float4 sg = *(const float4*)(s + sb + j0);
    const float4 su = *(const float4*)(s + sb + 4096 + j0);
    __half2 o[4];
    o[0] = __floats2half2_rn((gq.x-8)*sg.x, (uq.x-8)*su.x);
    o[1] = __floats2half2_rn((gq.y-8)*sg.y, (uq.y-8)*su.y);
    o[2] = __floats2half2_rn((gq.z-8)*sg.z, (uq.z-8)*su.z);
    o[3] = __floats2half2_rn((gq.w-8)*sg.w, (uq.w-8)*su.w);
    *(uint4*)(g_w1h + kl*8192 + (size_t)c8*8) = *(uint4*)o;
}

// ---------------- dequant w2 ----------------
__global__ void k_dq2(const int* __restrict__ q, const float* __restrict__ s){
    size_t gid = (size_t)blockIdx.x*blockDim.x + threadIdx.x;
    int n8 = (int)(gid & 127);
    size_t kl = gid >> 7;
    int k = (int)(kl & 4095); int e = (int)(kl >> 12);
    int n0 = n8*8;
    const int4 qa = *(const int4*)(q + kl*1024 + n0);
    const int4 qb = *(const int4*)(q + kl*1024 + n0 + 4);
    size_t sbase = ((size_t)e*32 + (k>>7))*1024;
    const float4 sa = *(const float4*)(s + sbase + n0);
    const float4 sb = *(const float4*)(s + sbase + n0 + 4);
    __half2 o[4];
    o[0] = __floats2half2_rn((qa.x-8)*sa.x, (qa.y-8)*sa.y);
    o[1] = __floats2half2_rn((qa.z-8)*sa.z, (qa.w-8)*sa.w);
    o[2] = __floats2half2_rn((qb.x-8)*sb.x, (qb.y-8)*sb.y);
    o[3] = __floats2half2_rn((qb.z-8)*sb.z, (qb.w-8)*sb.w);
    *(uint4*)(g_w2h + kl*1024 + n0) = *(uint4*)o;
}

// ---------------- grouped GEMM: TMA 3-stage + hoisted ldmatrix addressing ----------------
template<int PHASE>
__global__ __launch_bounds__(256,2) void k_gemm(float* __restrict__ out,
        const __grid_constant__ CUtensorMap mA, const __grid_constant__ CUtensorMap mB){
    constexpr int KDIM = (PHASE==1) ? D_ : F_;
    constexpr int NT   = (PHASE==1) ? (2*F_/BN) : (D_/BN);
    constexpr int NK   = KDIM/BK;

    const int bx = blockIdx.x;
    const int mt = bx & (MT_-1);
    const int rest = bx >> 4;
    const int nt = rest % NT;
    const int e  = rest / NT;
    const int cnt = g_cnt[e];
    const int mstart = mt*BM;
    if (mstart >= cnt) return;
    const int rowbase = e*CAP + mstart;

    extern __shared__ __align__(1024) char dsm[];
    const unsigned sbase = (smem_u32(dsm) + 1023u) & ~1023u;

    const int tid = threadIdx.x;
    const int lane = tid & 31, warp = tid >> 5;
    const int wm = warp & 3, wn = warp >> 2;

    if (tid == 0){
        #pragma unroll
        for (int s=0;s<STAGES;s++) mbar_init(sbase + MBAR_OFF + s*8, 1);
        asm volatile("fence.proxy.async.shared::cta;" ::: "memory");
    }
    __syncthreads();

    auto issue = [&](int st, int k0){
        unsigned aD = sbase + st*STAGE_BYTES;
        unsigned bD = aD + 16384;
        unsigned bar = sbase + MBAR_OFF + st*8;
        mbar_expect(bar, 32768);
        tma2d(aD,        &mA, k0,        rowbase,      bar);
        tma2d(bD,        &mB, nt*BN,     e*KDIM + k0,  bar);
        tma2d(bD + 8192, &mB, nt*BN+64,  e*KDIM + k0,  bar);
    };

    // ---- loop-invariant ldmatrix offsets (relative to stage base) ----
    // A (mi=0; mi=1 is +2048 since (row+16)&7 == row&7):
    //   addr = aS + row*128 + ((kk*2 + (lane>>4)) ^ (row&7))<<4
    unsigned offA[4];
    {
        int row = wm*32 + (lane & 15);
        int hi = lane >> 4;
        #pragma unroll
        for (int kk=0; kk<4; kk++)
            offA[kk] = (unsigned)(row*128 + (((kk*2 + hi) ^ (row & 7)) << 4));
    }
    // B: lr = kk*16 + lr0, lr&7 == lane&7 (kk-invariant). addr = bS + offB[nq] + kk*2048
    unsigned offB[4];
    {
        int lr0 = (((lane>>4)&1)<<3) + (lane & 7);
        #pragma unroll
        for (int nq=0; nq<4; nq++){
            int lc = wn*64 + nq*16 + (((lane>>3)&1)<<3);
            int blk = lc >> 6;
            int c6  = (lc >> 3) & 7;
            offB[nq] = (unsigned)(blk*8192 + lr0*128 + ((c6 ^ (lane & 7)) << 4));
        }
    }

    float acc[2][8][4];
    #pragma unroll
    for (int mi=0;mi<2;mi++)
        #pragma unroll
        for (int nj=0;nj<8;nj++)
            #pragma unroll
            for (int v=0;v<4;v++) acc[mi][nj][v] = 0.f;

    if (tid == 0){ issue(0, 0); issue(1, BK); }
    int phmask = 0;   // bit s = parity of stage s

    #pragma unroll 1
    for (int kt=0; kt<NK; kt++){
        const int s = kt % STAGES;
        if (tid == 0 && kt+2 < NK) issue((kt+2)%STAGES, (kt+2)*BK);
        mbar_wait(sbase + MBAR_OFF + s*8, (unsigned)((phmask >> s) & 1));
        phmask ^= (1 << s);

        const unsigned aS = sbase + s*STAGE_BYTES;
        const unsigned bS = aS + 16384;

        #pragma unroll
        for (int kk=0; kk<4; kk++){
            unsigned a[2][4];
            ldsm4(a[0][0],a[0][1],a[0][2],a[0][3], aS + offA[kk]);
            ldsm4(a[1][0],a[1][1],a[1][2],a[1][3], aS + offA[kk] + 2048);
            unsigned b[8][2];
            #pragma unroll
            for (int nq=0;nq<4;nq++){
                unsigned r0,r1,r2,r3;
                ldsm4t(r0,r1,r2,r3, bS + offB[nq] + kk*2048);
                b[2*nq  ][0]=r0; b[2*nq  ][1]=r2;
                b[2*nq+1][0]=r1; b[2*nq+1][1]=r3;
            }
            #pragma unroll
            for (int mi=0;mi<2;mi++)
                #pragma unroll
                for (int nj=0;nj<8;nj++)
                    mma16816(acc[mi][nj], a[mi][0],a[mi][1],a[mi][2],a[mi][3], b[nj][0],b[nj][1]);
        }
        __syncthreads();
    }

    if (PHASE==1){
        // fused SiLU(gate)*up: interleaved column pairs live in the same thread
        __half* stage = (__half*)(dsm + (sbase - smem_u32(dsm)));
        #pragma unroll
        for (int mi=0;mi<2;mi++){
            #pragma unroll
            for (int nj=0;nj<8;nj++){
                int r0 = wm*32 + mi*16 + (lane>>2);
                int c  = wn*32 + nj*4 + (lane&3);
                float g0=acc[mi][nj][0], u0=acc[mi][nj][1];
                float g1=acc[mi][nj][2], u1=acc[mi][nj][3];
                float a0 = g0/(1.f+__expf(-g0))*u0;
                float a1 = g1/(1.f+__expf(-g1))*u1;
                stage[r0*72 + c]     = __float2half(a0);
                stage[(r0+8)*72 + c] = __float2half(a1);
            }
        }
        __syncthreads();
        __half* dst = g_act + (size_t)rowbase*F_ + (size_t)nt*64;
        #pragma unroll
        for (int it=0; it<4; it++){
            int idx = it*256 + tid;
            int r = idx >> 3, cc = (idx & 7) << 3;
            *(uint4*)(dst + (size_t)r*F_ + cc) = *(uint4*)(stage + r*72 + cc);
        }
    } else {
        #pragma unroll
        for (int mi=0;mi<2;mi++){
            #pragma unroll
            for (int h=0;h<2;h++){
                int r = wm*32 + mi*16 + (lane>>2) + h*8;
                int srow = mstart + r;
                if (srow >= cnt) continue;
                int slot = e*CAP + srow;
                int tok = g_tok[slot];
                float cf = g_coef[slot];
                float* op = out + (size_t)tok*D_ + (size_t)nt*BN;
                #pragma unroll
                for (int nj=0;nj<8;nj++){
                    int c = wn*64 + nj*8 + ((lane&3)<<1);
                    atomicAdd(op + c,     cf*acc[mi][nj][h*2+0]);
                    atomicAdd(op + c + 1, cf*acc[mi][nj][h*2+1]);
                }
            }
        }
    }
}

// ---------------- host: tensormap setup + launch ----------------
typedef CUresult (CUDAAPI *EncodeFn)(CUtensorMap*, CUtensorMapDataType, cuuint32_t, void*,
    const cuuint64_t*, const cuuint64_t*, const cuuint32_t*, const cuuint32_t*,
    CUtensorMapInterleave, CUtensorMapSwizzle, CUtensorMapL2promotion, CUtensorMapFloatOOBfill);

static void build_map(EncodeFn enc, CUtensorMap* m, void* addr,
                      uint64_t inner, uint64_t outer, uint32_t box_in, uint32_t box_out){
    cuuint64_t dims[2]    = { inner, outer };
    cuuint64_t strides[1] = { inner * 2 };
    cuuint32_t box[2]     = { box_in, box_out };
    cuuint32_t estr[2]    = { 1, 1 };
    enc(m, CU_TENSOR_MAP_DATA_TYPE_UINT16, 2, addr, dims, strides, box, estr,
        CU_TENSOR_MAP_INTERLEAVE_NONE, CU_TENSOR_MAP_SWIZZLE_128B,
        CU_TENSOR_MAP_L2_PROMOTION_L2_128B, CU_TENSOR_MAP_FLOAT_OOB_FILL_NONE);
}

extern "C" void kernel_launch(void* const* d_in, const int* in_sizes, int n_in,
                              void* d_out, int out_size){
    const float* x      = (const float*)d_in[0];
    const float* gating = (const float*)d_in[1];
    const int*   w1q    = (const int*)d_in[2];
    const int*   w2q    = (const int*)d_in[3];
    const float* w1s    = (const float*)d_in[4];
    const float* w2s    = (const float*)d_in[5];
    float* out = (float*)d_out;

    static cudaStream_t s2 = nullptr;
    static cudaEvent_t e1, ej2;
    static CUtensorMap mXg, mAct, mW1, mW2;
    if (!s2){
        cudaFuncSetAttribute(k_gemm<1>, cudaFuncAttributeMaxDynamicSharedMemorySize, SMEM_BYTES);
        cudaFuncSetAttribute(k_gemm<2>, cudaFuncAttributeMaxDynamicSharedMemorySize, SMEM_BYTES);
        cudaStreamCreateWithFlags(&s2, cudaStreamNonBlocking);
        cudaEventCreateWithFlags(&e1,  cudaEventDisableTiming);
        cudaEventCreateWithFlags(&ej2, cudaEventDisableTiming);

        EncodeFn enc = nullptr;
        cudaDriverEntryPointQueryResult qr;
        cudaGetDriverEntryPoint("cuTensorMapEncodeTiled", (void**)&enc, cudaEnableDefault, &qr);
        void *pXg, *pAct, *pW1, *pW2;
        cudaGetSymbolAddress(&pXg,  g_xg);
        cudaGetSymbolAddress(&pAct, g_act);
        cudaGetSymbolAddress(&pW1,  g_w1h);
        cudaGetSymbolAddress(&pW2,  g_w2h);
        build_map(enc, &mXg,  pXg,  D_,    NSLOT,           64, 128);
        build_map(enc, &mAct, pAct, F_,    NSLOT,           64, 128);
        build_map(enc, &mW1,  pW1,  2*F_,  (uint64_t)E_*D_, 64, 64);
        build_map(enc, &mW2,  pW2,  D_,    (uint64_t)E_*F_, 64, 64);
    }

    k_dq1      <<<32768, 256>>>(w1q, w1s);             // launch 1 (also zeroes g_cnt)
    cudaEventRecord(e1, 0);
    k_route    <<<16,    256>>>(gating);               // launch 2
    k_gatherpad<<<T_+64, 128>>>(x);                    // launch 3
    k_gemm<1>  <<<E_*64*MT_, 256, SMEM_BYTES>>>(out, mXg, mW1);   // launch 4 <-- ncu target

    cudaStreamWaitEvent(s2, e1, 0);
    k_dq2      <<<16384, 256, 0, s2>>>(w2q, w2s);      // launch 5 (overlaps gemm1)
    k_zero     <<<4096,  256, 0, s2>>>(out);           // launch 6
    cudaEventRecord(ej2, s2);

    cudaStreamWaitEvent(0, ej2, 0);
    k_gemm<2>  <<<E_*8*MT_,  256, SMEM_BYTES>>>(out, mAct, mW2);  // launch 7
}